// round 7
// baseline (speedup 1.0000x reference)
#include <cuda_runtime.h>
#include <cstdint>
#include <cstddef>

#define TAME_F  100000.0f
#define TAME2_F 1.0e10f
#define NTHR    256

__device__ __forceinline__ float frsq(float x) {
    float r;
    asm("rsqrt.approx.f32 %0, %1;" : "=f"(r) : "f"(x));
    return r;
}

// One thread = one system. 16 blocks x 256 threads -> 8 warps/SM on 16 SMs =
// 2 warps per SMSP. The per-step dependency chain (~44 cyc: MUFU stagger+lat,
// s', x, h) leaves ~44 cyc of stall per warp that single-warp in-order issue
// cannot fill from within the warp (measured R1/R6: 77 cyc/step, issue 43%).
// A second warp on the same SMSP turns those stall cycles into its issue
// slots: the pair becomes issue-bound at ~2x31 = 62 cyc per joint step.
// MUFU (6 x rt8 = 48) and LSU (6 STG x 5 = 30) fit under that budget.
__global__ void __launch_bounds__(NTHR, 1)
tithte_kernel(const float* __restrict__ state0,
              const float* __restrict__ params,
              const float* __restrict__ ed,
              const int*   __restrict__ dtp,
              float*       __restrict__ out,
              int B, int T)
{
    extern __shared__ float4 sm4[];   // [0..T+1] rows {T_out, heat, solar, 0}

    const int tid = threadIdx.x;

    #pragma unroll 4
    for (int r = tid; r < T + 2; r += NTHR) {
        float4 v = make_float4(0.f, 0.f, 0.f, 0.f);
        if (r < T) { v.x = ed[3*r]; v.y = ed[3*r+1]; v.z = ed[3*r+2]; }
        sm4[r] = v;
    }
    __syncthreads();

    const int b = blockIdx.x * NTHR + tid;

    const float dtf = (float)dtp[0];
    const float C1 = params[b*6+0], R1 = params[b*6+1];
    const float C2 = params[b*6+2], R2 = params[b*6+3];
    const float C3 = params[b*6+4], R3 = params[b*6+5];

    const float a1 = dtf / C1, a2 = dtf / C2, a3 = dtf / C3;
    const float iR1 = 1.0f / R1, iR2 = 1.0f / R2, iR3 = 1.0f / R3;

    const float m12 = a1 * iR2, m13 = a1 * iR1, m11 = -(m12 + m13);
    const float m21 = a2 * iR2, m22 = -m21;
    const float m31 = a3 * iR1, k33 = a3 * iR3, m33 = -(m31 + k33);

    float s1 = state0[b*3+0], s2 = state0[b*3+1], s3 = state0[b*3+2];

    // prologue: x(0), h(0), tx(0) from row 0
    float4 row0 = sm4[0];
    float c1 = a1  * row0.z;
    float c2 = a2  * row0.y;
    float c3 = k33 * row0.x;
    float x1 = fmaf(m13, s3, fmaf(m12, s2, fmaf(m11, s1, c1)));
    float x2 = fmaf(m22, s2, fmaf(m21, s1, c2));
    float x3 = fmaf(m33, s3, fmaf(m31, s1, c3));
    float h1 = fmaf(x1, x1, TAME2_F), tx1 = x1 * TAME_F;
    float h2 = fmaf(x2, x2, TAME2_F), tx2 = x2 * TAME_F;
    float h3 = fmaf(x3, x3, TAME2_F), tx3 = x3 * TAME_F;

    float4 nr = sm4[1];               // prefetched row t+1

    float* op = out + (size_t)b * 3;
    const size_t grow = (size_t)B * 3;

    // ---- peeled iteration 0 (no deferred store yet) ----
    {
        const float r1 = frsq(h1);
        const float r2 = frsq(h2);
        const float r3 = frsq(h3);
        c1 = a1  * nr.z;
        c2 = a2  * nr.y;
        c3 = k33 * nr.x;
        nr = sm4[2];
        s1 = fmaf(tx1, r1, s1);
        s2 = fmaf(tx2, r2, s2);
        s3 = fmaf(tx3, r3, s3);
        x1 = fmaf(m13, s3, fmaf(m12, s2, fmaf(m11, s1, c1)));
        x2 = fmaf(m22, s2, fmaf(m21, s1, c2));
        x3 = fmaf(m33, s3, fmaf(m31, s1, c3));
        h1 = fmaf(x1, x1, TAME2_F); tx1 = x1 * TAME_F;
        h2 = fmaf(x2, x2, TAME2_F); tx2 = x2 * TAME_F;
        h3 = fmaf(x3, x3, TAME2_F); tx3 = x3 * TAME_F;
    }

    // steady state: at iteration t, store s(t-1) inside the MUFU-wait window.
    float p1 = s1, p2 = s2, p3 = s3;

    #pragma unroll 8
    for (int t = 1; t < T; ++t) {
        const float r1 = frsq(h1);   // r1 first: s1' gates every x
        const float r2 = frsq(h2);
        const float r3 = frsq(h3);

        // filler window: chain-independent work
        op[0] = p1; op[1] = p2; op[2] = p3;   // store s(t-1)
        op += grow;
        c1 = a1  * nr.z;                      // c(t+1)
        c2 = a2  * nr.y;
        c3 = k33 * nr.x;
        nr = sm4[t + 2];                      // prefetch row t+2 (zero-padded)

        // chain consumers
        s1 = fmaf(tx1, r1, s1);
        s2 = fmaf(tx2, r2, s2);
        s3 = fmaf(tx3, r3, s3);
        p1 = s1; p2 = s2; p3 = s3;

        x1 = fmaf(m13, s3, fmaf(m12, s2, fmaf(m11, s1, c1)));
        x2 = fmaf(m22, s2, fmaf(m21, s1, c2));
        x3 = fmaf(m33, s3, fmaf(m31, s1, c3));

        h1 = fmaf(x1, x1, TAME2_F); tx1 = x1 * TAME_F;
        h2 = fmaf(x2, x2, TAME2_F); tx2 = x2 * TAME_F;
        h3 = fmaf(x3, x3, TAME2_F); tx3 = x3 * TAME_F;
    }

    // final row T-1
    op[0] = p1; op[1] = p2; op[2] = p3;
}

extern "C" void kernel_launch(void* const* d_in, const int* in_sizes, int n_in,
                              void* d_out, int out_size) {
    const float* state0 = (const float*)d_in[0];
    const float* params = (const float*)d_in[1];
    const float* ed     = (const float*)d_in[2];
    const int*   dtp    = (const int*)d_in[3];
    float* out = (float*)d_out;

    const int B = in_sizes[0] / 3;   // (B, 3)
    const int T = in_sizes[2] / 3;   // (T, 3)

    const int blocks = B / NTHR;     // 16 -> 8 warps/SM -> 2 per SMSP
    const size_t smem = (size_t)(T + 2) * sizeof(float4);

    cudaFuncSetAttribute(tithte_kernel,
                         cudaFuncAttributeMaxDynamicSharedMemorySize, (int)smem);
    tithte_kernel<<<blocks, NTHR, smem>>>(state0, params, ed, dtp, out, B, T);
}

// round 8
// speedup vs baseline: 1.3175x; 1.3175x over previous
#include <cuda_runtime.h>
#include <cstdint>
#include <cstddef>

#define TAME_F  100000.0f
#define TAME2_F 1.0e10f
#define NTHR    128

typedef unsigned long long u64;

__device__ __forceinline__ float frsq(float x) {
    float r;
    asm("rsqrt.approx.f32 %0, %1;" : "=f"(r) : "f"(x));
    return r;
}
__device__ __forceinline__ u64 pk2(float lo, float hi) {
    u64 r;
    asm("mov.b64 %0, {%1, %2};" : "=l"(r) : "f"(lo), "f"(hi));
    return r;
}
__device__ __forceinline__ float lo2(u64 v) {
    float a, b;
    asm("mov.b64 {%0, %1}, %2;" : "=f"(a), "=f"(b) : "l"(v));
    return a;
}
__device__ __forceinline__ float hi2(u64 v) {
    float a, b;
    asm("mov.b64 {%0, %1}, %2;" : "=f"(a), "=f"(b) : "l"(v));
    return b;
}
__device__ __forceinline__ u64 fma2(u64 a, u64 b, u64 c) {
    u64 d;
    asm("fma.rn.f32x2 %0, %1, %2, %3;" : "=l"(d) : "l"(a), "l"(b), "l"(c));
    return d;
}
__device__ __forceinline__ u64 mul2(u64 a, u64 b) {
    u64 d;
    asm("mul.rn.f32x2 %0, %1, %2;" : "=l"(d) : "l"(a), "l"(b));
    return d;
}

// k=1, 32 blocks x 128 threads -> 128 warps on 128 distinct SMSPs (R7 proved
// co-residency only dilutes per-warp dispatch). R6 is dispatch-occupancy
// bound (~70 cyc/step: 21 FFMA x rt2 + 3 STG x 5 + ...). This round packs
// components (1,2) into f32x2 for the elementwise ops (h, tx, s', c) and the
// matvec, cutting fp instruction count 21 -> 13. Pair pack/unpack is free in
// SASS when ptxas allocates aligned pairs; only the 3 s-broadcasts are real
// MOVs. smem rows are reordered {solar, heat, T_out} so (x,y) of the LDS.128
// result is directly the aligned (solar,heat) pair feeding c12.
__global__ void __launch_bounds__(NTHR, 1)
tithte_kernel(const float* __restrict__ state0,
              const float* __restrict__ params,
              const float* __restrict__ ed,
              const int*   __restrict__ dtp,
              float*       __restrict__ out,
              int B, int T)
{
    extern __shared__ float4 sm4[];   // [0..T+1] rows {solar, heat, T_out, 0}

    const int tid = threadIdx.x;

    #pragma unroll 4
    for (int r = tid; r < T + 2; r += NTHR) {
        float4 v = make_float4(0.f, 0.f, 0.f, 0.f);
        if (r < T) { v.x = ed[3*r+2]; v.y = ed[3*r+1]; v.z = ed[3*r]; }
        sm4[r] = v;
    }
    __syncthreads();

    const int b = blockIdx.x * NTHR + tid;

    const float dtf = (float)dtp[0];
    const float C1 = params[b*6+0], R1 = params[b*6+1];
    const float C2 = params[b*6+2], R2 = params[b*6+3];
    const float C3 = params[b*6+4], R3 = params[b*6+5];

    const float a1 = dtf / C1, a2 = dtf / C2, a3 = dtf / C3;
    const float iR1 = 1.0f / R1, iR2 = 1.0f / R2, iR3 = 1.0f / R3;

    const float m12 = a1 * iR2, m13 = a1 * iR1, m11 = -(m12 + m13);
    const float m21 = a2 * iR2, m22 = -m21;
    const float m31 = a3 * iR1, k33 = a3 * iR3, m33 = -(m31 + k33);

    // packed column coefficients for (x1,x2):
    const u64 M1 = pk2(m11, m21);     // * s1
    const u64 M2 = pk2(m12, m22);     // * s2
    const u64 M3 = pk2(m13, 0.0f);    // * s3 (x2 has no s3 term)
    const u64 A12 = pk2(a1, a2);      // c12 = A12 * (solar, heat)
    const u64 T2P = pk2(TAME2_F, TAME2_F);
    const u64 TP  = pk2(TAME_F,  TAME_F);

    u64  s12 = pk2(state0[b*3+0], state0[b*3+1]);
    float s3 = state0[b*3+2];

    // prologue: x(0), h(0), tx(0) from row 0
    float4 row0 = sm4[0];
    u64  c12 = mul2(A12, pk2(row0.x, row0.y));
    float c3 = k33 * row0.z;
    u64  x12 = fma2(M3, pk2(s3, s3),
               fma2(M2, pk2(hi2(s12), hi2(s12)),
               fma2(M1, pk2(lo2(s12), lo2(s12)), c12)));
    float x3 = fmaf(m33, s3, fmaf(m31, lo2(s12), c3));
    u64  h12 = fma2(x12, x12, T2P);
    u64  tx12 = mul2(x12, TP);
    float h3 = fmaf(x3, x3, TAME2_F), tx3 = x3 * TAME_F;

    float4 nr = sm4[1];               // prefetched row t+1

    float* op = out + (size_t)b * 3;
    const size_t grow = (size_t)B * 3;

    // ---- peeled iteration 0 (no deferred store) ----
    {
        const float r1 = frsq(lo2(h12));
        const float r2 = frsq(hi2(h12));
        const float r3 = frsq(h3);
        c12 = mul2(A12, pk2(nr.x, nr.y));
        c3  = k33 * nr.z;
        nr  = sm4[2];
        s12 = fma2(tx12, pk2(r1, r2), s12);
        s3  = fmaf(tx3, r3, s3);
        x12 = fma2(M3, pk2(s3, s3),
              fma2(M2, pk2(hi2(s12), hi2(s12)),
              fma2(M1, pk2(lo2(s12), lo2(s12)), c12)));
        x3  = fmaf(m33, s3, fmaf(m31, lo2(s12), c3));
        h12 = fma2(x12, x12, T2P); tx12 = mul2(x12, TP);
        h3  = fmaf(x3, x3, TAME2_F); tx3 = x3 * TAME_F;
    }

    float p1 = lo2(s12), p2 = hi2(s12), p3 = s3;

    #pragma unroll 8
    for (int t = 1; t < T; ++t) {
        // rsqrt of components 1,2 first: s12' gates the packed matvec
        const float r1 = frsq(lo2(h12));
        const float r2 = frsq(hi2(h12));
        const float r3 = frsq(h3);

        // filler window: deferred store of s(t-1), c(t+1), prefetch
        op[0] = p1; op[1] = p2; op[2] = p3;
        op += grow;
        c12 = mul2(A12, pk2(nr.x, nr.y));  // (nr.x,nr.y) is an aligned pair
        c3  = k33 * nr.z;
        nr  = sm4[t + 2];                  // zero-padded past T

        // chain consumers
        s12 = fma2(tx12, pk2(r1, r2), s12);
        s3  = fmaf(tx3, r3, s3);
        p1 = lo2(s12); p2 = hi2(s12); p3 = s3;

        // packed matvec: broadcasts of s1, s2, s3 (the only real MOVs)
        x12 = fma2(M3, pk2(s3, s3),
              fma2(M2, pk2(hi2(s12), hi2(s12)),
              fma2(M1, pk2(lo2(s12), lo2(s12)), c12)));
        x3  = fmaf(m33, s3, fmaf(m31, lo2(s12), c3));

        h12 = fma2(x12, x12, T2P); tx12 = mul2(x12, TP);
        h3  = fmaf(x3, x3, TAME2_F); tx3 = x3 * TAME_F;
    }

    op[0] = p1; op[1] = p2; op[2] = p3;
}

extern "C" void kernel_launch(void* const* d_in, const int* in_sizes, int n_in,
                              void* d_out, int out_size) {
    const float* state0 = (const float*)d_in[0];
    const float* params = (const float*)d_in[1];
    const float* ed     = (const float*)d_in[2];
    const int*   dtp    = (const int*)d_in[3];
    float* out = (float*)d_out;

    const int B = in_sizes[0] / 3;   // (B, 3)
    const int T = in_sizes[2] / 3;   // (T, 3)

    const int blocks = B / NTHR;     // 32 -> 1 warp per SMSP chip-wide
    const size_t smem = (size_t)(T + 2) * sizeof(float4);

    cudaFuncSetAttribute(tithte_kernel,
                         cudaFuncAttributeMaxDynamicSharedMemorySize, (int)smem);
    tithte_kernel<<<blocks, NTHR, smem>>>(state0, params, ed, dtp, out, B, T);
}

// round 9
// speedup vs baseline: 1.3423x; 1.0188x over previous
#include <cuda_runtime.h>
#include <cstdint>
#include <cstddef>

#define TAME_F  100000.0f
#define TAME2_F 1.0e10f
#define NTHR    128

__device__ __forceinline__ float frsq(float x) {
    float r;
    asm("rsqrt.approx.f32 %0, %1;" : "=f"(r) : "f"(x));
    return r;
}

// k=1, 32 blocks x 128 threads: 128 warps on 128 distinct SMSPs (proven
// optimal placement, R7). Period is exposed-latency bound (R8: fewer instrs,
// same 77 cyc). This round reshapes the recurrence dataflow:
//   - rsqrt issue order r3,r2,r1  =>  s3 ready first, s1 LAST
//   - u-trees computed from early s2,s3 during the MUFU stagger window
//   - every x_i finishes with ONE fma on the late s1 (depth 4, was 12)
//   - all three h's complete together => clean back-to-back MUFU burst at the
//     bottom of the body; consumers at next iteration's top, with the
//     store/c/prefetch filler in between.
__global__ void __launch_bounds__(NTHR, 1)
tithte_kernel(const float* __restrict__ state0,
              const float* __restrict__ params,
              const float* __restrict__ ed,
              const int*   __restrict__ dtp,
              float*       __restrict__ out,
              int B, int T)
{
    extern __shared__ float4 sm4[];   // [0..T+1] rows {T_out, heat, solar, 0}

    const int tid = threadIdx.x;

    #pragma unroll 4
    for (int r = tid; r < T + 2; r += NTHR) {
        float4 v = make_float4(0.f, 0.f, 0.f, 0.f);
        if (r < T) { v.x = ed[3*r]; v.y = ed[3*r+1]; v.z = ed[3*r+2]; }
        sm4[r] = v;
    }
    __syncthreads();

    const int b = blockIdx.x * NTHR + tid;

    const float dtf = (float)dtp[0];
    const float C1 = params[b*6+0], R1 = params[b*6+1];
    const float C2 = params[b*6+2], R2 = params[b*6+3];
    const float C3 = params[b*6+4], R3 = params[b*6+5];

    const float a1 = dtf / C1, a2 = dtf / C2, a3 = dtf / C3;
    const float iR1 = 1.0f / R1, iR2 = 1.0f / R2, iR3 = 1.0f / R3;

    const float m12 = a1 * iR2, m13 = a1 * iR1, m11 = -(m12 + m13);
    const float m21 = a2 * iR2, m22 = -m21;
    const float m31 = a3 * iR1, k33 = a3 * iR3, m33 = -(m31 + k33);

    float s1 = state0[b*3+0], s2 = state0[b*3+1], s3 = state0[b*3+2];

    // ---- prologue: step-0 x, h, tx from row 0; issue r(0) ----
    float4 row0 = sm4[0];
    float c1 = a1  * row0.z;
    float c2 = a2  * row0.y;
    float c3 = k33 * row0.x;
    float u1 = fmaf(m12, s2, fmaf(m13, s3, c1));
    float u2 = fmaf(m22, s2, c2);
    float u3 = fmaf(m33, s3, c3);
    float x1 = fmaf(m11, s1, u1);
    float x2 = fmaf(m21, s1, u2);
    float x3 = fmaf(m31, s1, u3);
    float h1 = fmaf(x1, x1, TAME2_F), tx1 = x1 * TAME_F;
    float h2 = fmaf(x2, x2, TAME2_F), tx2 = x2 * TAME_F;
    float h3 = fmaf(x3, x3, TAME2_F), tx3 = x3 * TAME_F;
    float r3 = frsq(h3);       // r3 first: s3 feeds the u-trees next iter
    float r2 = frsq(h2);
    float r1 = frsq(h1);

    float4 nr = sm4[1];        // prefetched row 1

    float* op = out + (size_t)b * 3;
    const size_t grow = (size_t)B * 3;

    // ---- peeled t = 0 (no deferred store yet) ----
    {
        c1 = a1  * nr.z;
        c2 = a2  * nr.y;
        c3 = k33 * nr.x;
        nr = sm4[2];
        s3 = fmaf(tx3, r3, s3);       // arrival order: s3 first, s1 last
        s2 = fmaf(tx2, r2, s2);
        s1 = fmaf(tx1, r1, s1);
        u1 = fmaf(m12, s2, fmaf(m13, s3, c1));
        u2 = fmaf(m22, s2, c2);
        u3 = fmaf(m33, s3, c3);
        x1 = fmaf(m11, s1, u1);
        x2 = fmaf(m21, s1, u2);
        x3 = fmaf(m31, s1, u3);
        h1 = fmaf(x1, x1, TAME2_F); tx1 = x1 * TAME_F;
        h2 = fmaf(x2, x2, TAME2_F); tx2 = x2 * TAME_F;
        h3 = fmaf(x3, x3, TAME2_F); tx3 = x3 * TAME_F;
        r3 = frsq(h3);
        r2 = frsq(h2);
        r1 = frsq(h1);
    }

    float p1 = s1, p2 = s2, p3 = s3;   // s(0), stored during t=1

    #pragma unroll 8
    for (int t = 1; t < T; ++t) {
        // filler between the in-flight MUFUs and their consumers
        op[0] = p1; op[1] = p2; op[2] = p3;   // store s(t-1)
        op += grow;
        c1 = a1  * nr.z;                      // c(t+1)
        c2 = a2  * nr.y;
        c3 = k33 * nr.x;
        nr = sm4[t + 2];                      // prefetch (zero-padded)

        // consume r(t) in arrival order
        s3 = fmaf(tx3, r3, s3);
        s2 = fmaf(tx2, r2, s2);
        s1 = fmaf(tx1, r1, s1);
        p1 = s1; p2 = s2; p3 = s3;

        // u-trees from early s2,s3 (fill the MUFU stagger window), then one
        // shallow fma on the late s1 finishes every x
        u1 = fmaf(m12, s2, fmaf(m13, s3, c1));
        u2 = fmaf(m22, s2, c2);
        u3 = fmaf(m33, s3, c3);
        x1 = fmaf(m11, s1, u1);
        x2 = fmaf(m21, s1, u2);
        x3 = fmaf(m31, s1, u3);

        h1 = fmaf(x1, x1, TAME2_F); tx1 = x1 * TAME_F;
        h2 = fmaf(x2, x2, TAME2_F); tx2 = x2 * TAME_F;
        h3 = fmaf(x3, x3, TAME2_F); tx3 = x3 * TAME_F;

        // issue r(t+1) burst at the bottom: maximal distance to consumers
        r3 = frsq(h3);
        r2 = frsq(h2);
        r1 = frsq(h1);
    }

    op[0] = p1; op[1] = p2; op[2] = p3;       // row T-1
}

extern "C" void kernel_launch(void* const* d_in, const int* in_sizes, int n_in,
                              void* d_out, int out_size) {
    const float* state0 = (const float*)d_in[0];
    const float* params = (const float*)d_in[1];
    const float* ed     = (const float*)d_in[2];
    const int*   dtp    = (const int*)d_in[3];
    float* out = (float*)d_out;

    const int B = in_sizes[0] / 3;   // (B, 3)
    const int T = in_sizes[2] / 3;   // (T, 3)

    const int blocks = B / NTHR;     // 32 -> 1 warp per SMSP chip-wide
    const size_t smem = (size_t)(T + 2) * sizeof(float4);

    cudaFuncSetAttribute(tithte_kernel,
                         cudaFuncAttributeMaxDynamicSharedMemorySize, (int)smem);
    tithte_kernel<<<blocks, NTHR, smem>>>(state0, params, ed, dtp, out, B, T);
}

// round 10
// speedup vs baseline: 1.3454x; 1.0023x over previous
#include <cuda_runtime.h>
#include <cstdint>
#include <cstddef>

#define TAME_F  100000.0f
#define TAME2_F 1.0e10f
#define NTHR    128

__device__ __forceinline__ float frsq(float x) {
    float r;
    asm("rsqrt.approx.f32 %0, %1;" : "=f"(r) : "f"(x));
    return r;
}

// k=1, 32 blocks x 128 threads: 128 warps on 128 distinct SMSPs.
// The loop is dispatch-occupancy bound (~75 cyc/step measured vs ledger:
// 21 FFMA x rt2 + 3 STG x 5 + MUFU burst stalls + LDS + loop). This round
// trims the ledger: 19 fp ops (not 21), tame-muls in FFMA-imm form (rt 1),
// and the three MUFU.RSQ issues interleaved with the h/tx stream so the
// MUFU rt-8 structural stalls are filled with useful instructions.
__global__ void __launch_bounds__(NTHR, 1)
tithte_kernel(const float* __restrict__ state0,
              const float* __restrict__ params,
              const float* __restrict__ ed,
              const int*   __restrict__ dtp,
              float*       __restrict__ out,
              int B, int T)
{
    extern __shared__ float4 sm4[];   // [0..T+1] rows {T_out, heat, solar, 0}

    const int tid = threadIdx.x;

    #pragma unroll 4
    for (int r = tid; r < T + 2; r += NTHR) {
        float4 v = make_float4(0.f, 0.f, 0.f, 0.f);
        if (r < T) { v.x = ed[3*r]; v.y = ed[3*r+1]; v.z = ed[3*r+2]; }
        sm4[r] = v;
    }
    __syncthreads();

    const int b = blockIdx.x * NTHR + tid;

    const float dtf = (float)dtp[0];
    const float C1 = params[b*6+0], R1 = params[b*6+1];
    const float C2 = params[b*6+2], R2 = params[b*6+3];
    const float C3 = params[b*6+4], R3 = params[b*6+5];

    const float a1 = dtf / C1, a2 = dtf / C2, a3 = dtf / C3;
    const float iR1 = 1.0f / R1, iR2 = 1.0f / R2, iR3 = 1.0f / R3;

    const float m12 = a1 * iR2, m13 = a1 * iR1, m11 = -(m12 + m13);
    const float m21 = a2 * iR2, m22 = -m21;
    const float m31 = a3 * iR1, k33 = a3 * iR3, m33 = -(m31 + k33);

    float s1 = state0[b*3+0], s2 = state0[b*3+1], s3 = state0[b*3+2];

    // ---- prologue: step-0 x, h, tx from row 0; issue r(0) interleaved ----
    float4 row0 = sm4[0];
    float c1 = a1  * row0.z;
    float c2 = a2  * row0.y;
    float c3 = k33 * row0.x;
    float u1 = fmaf(m12, s2, fmaf(m13, s3, c1));
    float u2 = fmaf(m22, s2, c2);
    float u3 = fmaf(m33, s3, c3);
    float x1 = fmaf(m11, s1, u1);
    float x2 = fmaf(m21, s1, u2);
    float x3 = fmaf(m31, s1, u3);
    float h3 = fmaf(x3, x3, TAME2_F);
    float r3 = frsq(h3);
    float tx3 = x3 * TAME_F;
    float h2 = fmaf(x2, x2, TAME2_F);
    float r2 = frsq(h2);
    float tx2 = x2 * TAME_F;
    float h1 = fmaf(x1, x1, TAME2_F);
    float r1 = frsq(h1);
    float tx1 = x1 * TAME_F;

    float4 nr = sm4[1];        // prefetched row 1

    float* op = out + (size_t)b * 3;
    const size_t grow = (size_t)B * 3;

    // ---- peeled t = 0 (no store of a previous row yet) ----
    {
        c1 = a1  * nr.z;
        c2 = a2  * nr.y;
        c3 = k33 * nr.x;
        nr = sm4[2];
        s3 = fmaf(tx3, r3, s3);
        s2 = fmaf(tx2, r2, s2);
        s1 = fmaf(tx1, r1, s1);
        u1 = fmaf(m12, s2, fmaf(m13, s3, c1));
        u2 = fmaf(m22, s2, c2);
        u3 = fmaf(m33, s3, c3);
        x1 = fmaf(m11, s1, u1);
        x2 = fmaf(m21, s1, u2);
        x3 = fmaf(m31, s1, u3);
        h3 = fmaf(x3, x3, TAME2_F);
        r3 = frsq(h3);
        tx3 = x3 * TAME_F;
        h2 = fmaf(x2, x2, TAME2_F);
        r2 = frsq(h2);
        tx2 = x2 * TAME_F;
        h1 = fmaf(x1, x1, TAME2_F);
        r1 = frsq(h1);
        tx1 = x1 * TAME_F;
    }

    // steady state: at iteration t, s holds s(t-1); store it (filler for the
    // in-flight MUFUs issued at the bottom of the previous iteration), then
    // consume r(t-1..) to advance.
    #pragma unroll 8
    for (int t = 1; t < T; ++t) {
        // filler window: store s(t-1) while MUFUs are in flight
        op[0] = s1; op[1] = s2; op[2] = s3;
        op += grow;
        c1 = a1  * nr.z;                      // c(t+1)
        c2 = a2  * nr.y;
        c3 = k33 * nr.x;
        nr = sm4[t + 2];                      // prefetch (zero-padded)

        // consume r in arrival order (r3 issued first)
        s3 = fmaf(tx3, r3, s3);
        s2 = fmaf(tx2, r2, s2);
        s1 = fmaf(tx1, r1, s1);

        // u-trees from early s2,s3; one shallow fma on the late s1 per x
        u1 = fmaf(m12, s2, fmaf(m13, s3, c1));
        u2 = fmaf(m22, s2, c2);
        u3 = fmaf(m33, s3, c3);
        x1 = fmaf(m11, s1, u1);
        x2 = fmaf(m21, s1, u2);
        x3 = fmaf(m31, s1, u3);

        // h -> MUFU interleaved with tx/h stream (no back-to-back MUFU burst)
        h3 = fmaf(x3, x3, TAME2_F);
        r3 = frsq(h3);
        tx3 = x3 * TAME_F;                    // FFMA-imm form, rt 1
        h2 = fmaf(x2, x2, TAME2_F);
        r2 = frsq(h2);
        tx2 = x2 * TAME_F;
        h1 = fmaf(x1, x1, TAME2_F);
        r1 = frsq(h1);
        tx1 = x1 * TAME_F;
    }

    op[0] = s1; op[1] = s2; op[2] = s3;       // row T-1
}

extern "C" void kernel_launch(void* const* d_in, const int* in_sizes, int n_in,
                              void* d_out, int out_size) {
    const float* state0 = (const float*)d_in[0];
    const float* params = (const float*)d_in[1];
    const float* ed     = (const float*)d_in[2];
    const int*   dtp    = (const int*)d_in[3];
    float* out = (float*)d_out;

    const int B = in_sizes[0] / 3;   // (B, 3)
    const int T = in_sizes[2] / 3;   // (T, 3)

    const int blocks = B / NTHR;     // 32 -> 1 warp per SMSP chip-wide
    const size_t smem = (size_t)(T + 2) * sizeof(float4);

    cudaFuncSetAttribute(tithte_kernel,
                         cudaFuncAttributeMaxDynamicSharedMemorySize, (int)smem);
    tithte_kernel<<<blocks, NTHR, smem>>>(state0, params, ed, dtp, out, B, T);
}